// round 1
// baseline (speedup 1.0000x reference)
#include <cuda_runtime.h>

#define NN 8192
#define D 64
#define DO 128
#define K 16
#define SEG 4
#define JSEG (NN/SEG)
#define TJ 32

// Scratch (no allocs allowed in kernel_launch)
__device__ float g_sq[NN];
__device__ float g_p[NN * DO];
__device__ float g_q[NN * DO];
__device__ unsigned long long g_ck[NN * SEG * K];

// ---------------------------------------------------------------------------
// Kernel 1: per-row squared norms + p = x@(W1a-W1b)+b1, q = x@W1b
// Block: 256 threads handles 8 rows of x. Thread c<128 -> p channel c,
// thread c>=128 -> q channel c-128.
// ---------------------------------------------------------------------------
__global__ __launch_bounds__(256) void pq_kernel(const float* __restrict__ x,
                                                 const float* __restrict__ W1,
                                                 const float* __restrict__ b1) {
    __shared__ float sx[8 * D];
    const int i0 = blockIdx.x * 8;
    const int t = threadIdx.x;

    for (int u = t; u < 8 * D; u += 256) sx[u] = x[i0 * D + u];
    __syncthreads();

    if (t < 8) {
        float s = 0.f;
        #pragma unroll
        for (int d = 0; d < D; d++) { float v = sx[t * D + d]; s = fmaf(v, v, s); }
        g_sq[i0 + t] = s;
    }

    float acc[8];
    #pragma unroll
    for (int m = 0; m < 8; m++) acc[m] = 0.f;

    if (t < DO) {
        const int c = t;
        for (int d = 0; d < D; d++) {
            float w = W1[d * DO + c] - W1[(D + d) * DO + c];
            #pragma unroll
            for (int m = 0; m < 8; m++) acc[m] = fmaf(sx[m * D + d], w, acc[m]);
        }
        float bb = b1[c];
        #pragma unroll
        for (int m = 0; m < 8; m++) g_p[(size_t)(i0 + m) * DO + c] = acc[m] + bb;
    } else {
        const int c = t - DO;
        for (int d = 0; d < D; d++) {
            float w = W1[(D + d) * DO + c];
            #pragma unroll
            for (int m = 0; m < 8; m++) acc[m] = fmaf(sx[m * D + d], w, acc[m]);
        }
        #pragma unroll
        for (int m = 0; m < 8; m++) g_q[(size_t)(i0 + m) * DO + c] = acc[m];
    }
}

// ---------------------------------------------------------------------------
// Kernel 2: kNN. grid = (N/128, SEG). Each thread owns one query row i and
// scans j in [s*JSEG, (s+1)*JSEG), keeping a sorted top-16 in registers.
// dist = sq_i + sq_j - 2*dot(x_i, x_j)  (matches reference formula in fp32).
// Partial lists written as uint64 keys (total-order float bits << 32 | j).
// ---------------------------------------------------------------------------
__global__ __launch_bounds__(128) void knn_kernel(const float* __restrict__ x) {
    __shared__ float4 sj[TJ * 16];
    __shared__ float ssq[TJ];
    const int tid = threadIdx.x;
    const int i = blockIdx.x * 128 + tid;
    const int s = blockIdx.y;

    float4 xi[16];
    const float4* xr = reinterpret_cast<const float4*>(x) + (size_t)i * 16;
    #pragma unroll
    for (int c = 0; c < 16; c++) xi[c] = xr[c];
    const float sqi = g_sq[i];

    float kd[K];
    int   kj[K];
    #pragma unroll
    for (int n = 0; n < K; n++) { kd[n] = 3.4e38f; kj[n] = 0; }

    const int jbeg = s * JSEG, jend = jbeg + JSEG;
    for (int jb = jbeg; jb < jend; jb += TJ) {
        const float4* gs = reinterpret_cast<const float4*>(x) + (size_t)jb * 16;
        for (int u = tid; u < TJ * 16; u += 128) sj[u] = gs[u];
        if (tid < TJ) ssq[tid] = g_sq[jb + tid];
        __syncthreads();

        #pragma unroll 2
        for (int jj = 0; jj < TJ; jj++) {
            float ax = 0.f, ay = 0.f, az = 0.f, aw = 0.f;
            #pragma unroll
            for (int c = 0; c < 16; c++) {
                float4 v = sj[jj * 16 + c];
                ax = fmaf(xi[c].x, v.x, ax);
                ay = fmaf(xi[c].y, v.y, ay);
                az = fmaf(xi[c].z, v.z, az);
                aw = fmaf(xi[c].w, v.w, aw);
            }
            float dot = (ax + ay) + (az + aw);
            float dist = fmaf(-2.f, dot, sqi + ssq[jj]);
            if (dist < kd[K - 1]) {
                kd[K - 1] = dist; kj[K - 1] = jb + jj;
                #pragma unroll
                for (int n = K - 1; n > 0; n--) {
                    if (kd[n] < kd[n - 1]) {
                        float td = kd[n]; kd[n] = kd[n - 1]; kd[n - 1] = td;
                        int   tj = kj[n]; kj[n] = kj[n - 1]; kj[n - 1] = tj;
                    }
                }
            }
        }
        __syncthreads();
    }

    unsigned long long* dst = g_ck + ((size_t)i * SEG + s) * K;
    #pragma unroll
    for (int n = 0; n < K; n++) {
        unsigned u = __float_as_uint(kd[n]);
        u = (u & 0x80000000u) ? ~u : (u | 0x80000000u);  // total order for floats
        dst[n] = ((unsigned long long)u << 32) | (unsigned)kj[n];
    }
}

// ---------------------------------------------------------------------------
// Kernel 3: per row i: merge 4x16 candidates -> final 16 neighbors (rank sort,
// keys unique), aggregate r = mean_n relu(p_i + q_jn), out = r@W2 + b2.
// Block = 128 threads = one output row.
// ---------------------------------------------------------------------------
__global__ __launch_bounds__(128) void agg_kernel(const float* __restrict__ W2,
                                                  const float* __restrict__ b2,
                                                  float* __restrict__ out) {
    __shared__ unsigned long long skey[SEG * K];
    __shared__ int snbr[K];
    __shared__ float sr[DO];
    const int i = blockIdx.x;
    const int t = threadIdx.x;

    if (t < SEG * K) skey[t] = g_ck[(size_t)i * SEG * K + t];
    __syncthreads();
    if (t < SEG * K) {
        unsigned long long mk = skey[t];
        int rank = 0;
        #pragma unroll
        for (int u = 0; u < SEG * K; u++) rank += (skey[u] < mk);
        if (rank < K) snbr[rank] = (int)(mk & 0xFFFFFFFFull);
    }
    __syncthreads();

    float p = g_p[(size_t)i * DO + t];
    float acc = 0.f;
    #pragma unroll
    for (int n = 0; n < K; n++) {
        int j = snbr[n];
        acc += fmaxf(p + g_q[(size_t)j * DO + t], 0.f);
    }
    sr[t] = acc * (1.f / K);
    __syncthreads();

    float o = b2[t];
    #pragma unroll 8
    for (int d = 0; d < DO; d++)
        o = fmaf(sr[d], W2[d * DO + t], o);
    out[(size_t)i * DO + t] = o;
}

// ---------------------------------------------------------------------------
extern "C" void kernel_launch(void* const* d_in, const int* in_sizes, int n_in,
                              void* d_out, int out_size) {
    const float* x  = (const float*)d_in[0];
    const float* W1 = (const float*)d_in[1];
    const float* b1 = (const float*)d_in[2];
    const float* W2 = (const float*)d_in[3];
    const float* b2 = (const float*)d_in[4];
    float* out = (float*)d_out;

    pq_kernel<<<NN / 8, 256>>>(x, W1, b1);
    knn_kernel<<<dim3(NN / 128, SEG), 128>>>(x);
    agg_kernel<<<NN, 128>>>(W2, b2, out);
}

// round 2
// speedup vs baseline: 1.1676x; 1.1676x over previous
#include <cuda_runtime.h>

#define NN 8192
#define D 64
#define DO 128
#define K 16
#define SEG 8
#define JSEG (NN/SEG)
#define TJ 64

// Scratch (no allocs allowed in kernel_launch)
__device__ float g_sq[NN];
__device__ float g_p[NN * DO];
__device__ float g_q[NN * DO];
__device__ unsigned long long g_ck[NN * SEG * K];

// Packed fp32x2 math (Blackwell FFMA2 path — only reachable via PTX)
__device__ __forceinline__ unsigned long long ffma2(unsigned long long a,
                                                    unsigned long long b,
                                                    unsigned long long c) {
    unsigned long long d;
    asm("fma.rn.f32x2 %0, %1, %2, %3;" : "=l"(d) : "l"(a), "l"(b), "l"(c));
    return d;
}
__device__ __forceinline__ unsigned long long fadd2(unsigned long long a,
                                                    unsigned long long b) {
    unsigned long long d;
    asm("add.rn.f32x2 %0, %1, %2;" : "=l"(d) : "l"(a), "l"(b));
    return d;
}

// ---------------------------------------------------------------------------
// Kernel 1: per-row squared norms + p = x@(W1a-W1b)+b1, q = x@W1b
// ---------------------------------------------------------------------------
__global__ __launch_bounds__(256) void pq_kernel(const float* __restrict__ x,
                                                 const float* __restrict__ W1,
                                                 const float* __restrict__ b1) {
    __shared__ float sx[8 * D];
    const int i0 = blockIdx.x * 8;
    const int t = threadIdx.x;

    for (int u = t; u < 8 * D; u += 256) sx[u] = x[i0 * D + u];
    __syncthreads();

    if (t < 8) {
        float s = 0.f;
        #pragma unroll
        for (int d = 0; d < D; d++) { float v = sx[t * D + d]; s = fmaf(v, v, s); }
        g_sq[i0 + t] = s;
    }

    float acc[8];
    #pragma unroll
    for (int m = 0; m < 8; m++) acc[m] = 0.f;

    if (t < DO) {
        const int c = t;
        for (int d = 0; d < D; d++) {
            float w = W1[d * DO + c] - W1[(D + d) * DO + c];
            #pragma unroll
            for (int m = 0; m < 8; m++) acc[m] = fmaf(sx[m * D + d], w, acc[m]);
        }
        float bb = b1[c];
        #pragma unroll
        for (int m = 0; m < 8; m++) g_p[(size_t)(i0 + m) * DO + c] = acc[m] + bb;
    } else {
        const int c = t - DO;
        for (int d = 0; d < D; d++) {
            float w = W1[(D + d) * DO + c];
            #pragma unroll
            for (int m = 0; m < 8; m++) acc[m] = fmaf(sx[m * D + d], w, acc[m]);
        }
        #pragma unroll
        for (int m = 0; m < 8; m++) g_q[(size_t)(i0 + m) * DO + c] = acc[m];
    }
}

// ---------------------------------------------------------------------------
// Kernel 2: kNN with packed f32x2 FMA along the D dimension.
// grid = (N/128, SEG). Each thread owns one query row i, scans JSEG j's,
// keeping a sorted top-16 in registers. Pairs (x[2d], x[2d+1]) live in b64
// regs; x_j rows are staged in shared verbatim and read as ulonglong2.
// ---------------------------------------------------------------------------
__global__ __launch_bounds__(128, 4) void knn_kernel(const float* __restrict__ x) {
    __shared__ ulonglong2 sj[TJ * 16];   // TJ rows x 256B, verbatim row copies
    __shared__ float ssq[TJ];
    const int tid = threadIdx.x;
    const int i = blockIdx.x * 128 + tid;
    const int s = blockIdx.y;

    // Query row packed as 16x ulonglong2 (32 f32x2 pairs) in registers.
    ulonglong2 xi[16];
    const ulonglong2* xr = reinterpret_cast<const ulonglong2*>(x) + (size_t)i * 16;
    #pragma unroll
    for (int c = 0; c < 16; c++) xi[c] = xr[c];
    const float sqi = g_sq[i];

    float kd[K];
    int   kj[K];
    #pragma unroll
    for (int n = 0; n < K; n++) { kd[n] = 3.4e38f; kj[n] = 0; }

    const int jbeg = s * JSEG, jend = jbeg + JSEG;
    for (int jb = jbeg; jb < jend; jb += TJ) {
        const ulonglong2* gs = reinterpret_cast<const ulonglong2*>(x) + (size_t)jb * 16;
        #pragma unroll
        for (int u = tid; u < TJ * 16; u += 128) sj[u] = gs[u];
        if (tid < TJ) ssq[tid] = g_sq[jb + tid];
        __syncthreads();

        #pragma unroll 2
        for (int jj = 0; jj < TJ; jj++) {
            unsigned long long a0 = 0ull, a1 = 0ull, a2 = 0ull, a3 = 0ull;
            #pragma unroll
            for (int c = 0; c < 16; c += 2) {
                ulonglong2 v0 = sj[jj * 16 + c];
                ulonglong2 v1 = sj[jj * 16 + c + 1];
                a0 = ffma2(xi[c].x, v0.x, a0);
                a1 = ffma2(xi[c].y, v0.y, a1);
                a2 = ffma2(xi[c + 1].x, v1.x, a2);
                a3 = ffma2(xi[c + 1].y, v1.y, a3);
            }
            unsigned long long st = fadd2(fadd2(a0, a1), fadd2(a2, a3));
            unsigned lo, hi;
            asm("mov.b64 {%0, %1}, %2;" : "=r"(lo), "=r"(hi) : "l"(st));
            float dot = __uint_as_float(lo) + __uint_as_float(hi);
            float dist = fmaf(-2.f, dot, sqi + ssq[jj]);
            if (dist < kd[K - 1]) {
                kd[K - 1] = dist; kj[K - 1] = jb + jj;
                #pragma unroll
                for (int n = K - 1; n > 0; n--) {
                    if (kd[n] < kd[n - 1]) {
                        float td = kd[n]; kd[n] = kd[n - 1]; kd[n - 1] = td;
                        int   tj = kj[n]; kj[n] = kj[n - 1]; kj[n - 1] = tj;
                    }
                }
            }
        }
        __syncthreads();
    }

    unsigned long long* dst = g_ck + ((size_t)i * SEG + s) * K;
    #pragma unroll
    for (int n = 0; n < K; n++) {
        unsigned u = __float_as_uint(kd[n]);
        u = (u & 0x80000000u) ? ~u : (u | 0x80000000u);  // total order for floats
        dst[n] = ((unsigned long long)u << 32) | (unsigned)kj[n];
    }
}

// ---------------------------------------------------------------------------
// Kernel 3: per row i: merge SEG x 16 candidates -> final 16 neighbors
// (rank select, keys unique), aggregate r = mean_n relu(p_i + q_jn),
// out = r@W2 + b2. Block = 128 threads = one output row.
// ---------------------------------------------------------------------------
__global__ __launch_bounds__(128) void agg_kernel(const float* __restrict__ W2,
                                                  const float* __restrict__ b2,
                                                  float* __restrict__ out) {
    __shared__ unsigned long long skey[SEG * K];
    __shared__ int snbr[K];
    __shared__ float sr[DO];
    const int i = blockIdx.x;
    const int t = threadIdx.x;

    skey[t] = g_ck[(size_t)i * SEG * K + t];
    __syncthreads();
    {
        unsigned long long mk = skey[t];
        int rank = 0;
        #pragma unroll 4
        for (int u = 0; u < SEG * K; u++) rank += (skey[u] < mk);
        if (rank < K) snbr[rank] = (int)(mk & 0xFFFFFFFFull);
    }
    __syncthreads();

    float p = g_p[(size_t)i * DO + t];
    float acc = 0.f;
    #pragma unroll
    for (int n = 0; n < K; n++) {
        int j = snbr[n];
        acc += fmaxf(p + g_q[(size_t)j * DO + t], 0.f);
    }
    sr[t] = acc * (1.f / K);
    __syncthreads();

    float o = b2[t];
    #pragma unroll 8
    for (int d = 0; d < DO; d++)
        o = fmaf(sr[d], W2[d * DO + t], o);
    out[(size_t)i * DO + t] = o;
}

// ---------------------------------------------------------------------------
extern "C" void kernel_launch(void* const* d_in, const int* in_sizes, int n_in,
                              void* d_out, int out_size) {
    const float* x  = (const float*)d_in[0];
    const float* W1 = (const float*)d_in[1];
    const float* b1 = (const float*)d_in[2];
    const float* W2 = (const float*)d_in[3];
    const float* b2 = (const float*)d_in[4];
    float* out = (float*)d_out;

    pq_kernel<<<NN / 8, 256>>>(x, W1, b1);
    knn_kernel<<<dim3(NN / 128, SEG), 128>>>(x);
    agg_kernel<<<NN, 128>>>(W2, b2, out);
}